// round 12
// baseline (speedup 1.0000x reference)
#include <cuda_runtime.h>
#include <cstdint>

#define C_DIM 128
#define K_NB  32
#define MAX_N 100000
#define WP_STRIDE 129   // u64 stride for packed-W smem rows (pad kills STS conflicts)

// Scratch (no-alloc rule: __device__ globals)
__device__ float g_supports[(size_t)MAX_N * C_DIM];

typedef unsigned long long u64;

__device__ __forceinline__ u64 pack2(float lo, float hi) {
    u64 r;
    asm("mov.b64 %0, {%1, %2};" : "=l"(r) : "f"(lo), "f"(hi));
    return r;
}
__device__ __forceinline__ void fma2(u64 &d, u64 a, u64 b) {
    asm("fma.rn.f32x2 %0, %1, %2, %0;" : "+l"(d) : "l"(a), "l"(b));
}
__device__ __forceinline__ float2 unpack2(u64 v) {
    float2 f;
    asm("mov.b64 {%0, %1}, %2;" : "=f"(f.x), "=f"(f.y) : "l"(v));
    return f;
}

// ---------------------------------------------------------------------------
// Kernel 1: supports = leaky_relu(word_vec @ W^T + b, 0.2)
// 64 rows/block, 256 threads, 2 blocks/SM. Thread = 8 rows x 4 colgroups,
// K-packed FFMA2 (acc lanes hold even/odd-c partials, summed at the end).
// acc = 32 u64 = 64 regs -> no spills (the round-10 regression was 128 regs
// of acc at 1 block/SM).
// Smem: Wp = u64 c-pairs [64][WP_STRIDE] (conflict-free LDS.64 w-loads),
//       xs = float [64][128] (x tile; ulonglong2 broadcast reads; reused as
//       output staging so global stores stay float4-coalesced).
// Per c4-step/warp: 8 LDS.64 + 8 LDS.128-bcast vs 64 FFMA2 -> FFMA2-bound.
// ---------------------------------------------------------------------------
__global__ __launch_bounds__(256, 2) void proj_kernel(
    const float* __restrict__ x,
    const float* __restrict__ W,
    const float* __restrict__ bias,
    float* __restrict__ out,
    int N)
{
    extern __shared__ char smem_raw[];
    u64*   Wp = (u64*)smem_raw;                             // [64][WP_STRIDE]
    float* xs = (float*)(smem_raw + 64 * WP_STRIDE * 8);    // [64][128]

    const int tx  = threadIdx.x;
    const int ty  = threadIdx.y;
    const int tid = ty * 32 + tx;
    const int rowBase = blockIdx.x * 64;

    // Pack W into c-pair u64s: Wp[c2][col] = (W[col][2c2], W[col][2c2+1]).
    #pragma unroll
    for (int i = tid; i < C_DIM * 32; i += 256) {
        int col = i >> 5;
        int c4  = i & 31;
        float4 v = ((const float4*)(W + (size_t)col * C_DIM))[c4];
        Wp[(2 * c4 + 0) * WP_STRIDE + col] = pack2(v.x, v.y);
        Wp[(2 * c4 + 1) * WP_STRIDE + col] = pack2(v.z, v.w);
    }

    // Load 64-row x tile (float4 coalesced, zero-pad tail).
    #pragma unroll
    for (int i = tid; i < 64 * 32; i += 256) {
        int r  = i >> 5;
        int c4 = i & 31;
        int row = rowBase + r;
        float4 v = make_float4(0.f, 0.f, 0.f, 0.f);
        if (row < N) v = ((const float4*)(x + (size_t)row * C_DIM))[c4];
        ((float4*)(xs + r * C_DIM))[c4] = v;
    }
    __syncthreads();

    u64 acc[8][4];
    #pragma unroll
    for (int r = 0; r < 8; r++)
        #pragma unroll
        for (int m = 0; m < 4; m++) acc[r][m] = 0ull;

    const float* xrow = xs + (ty * 8) * C_DIM;

    #pragma unroll 4
    for (int c4 = 0; c4 < 32; c4++) {
        const u64* wa = Wp + (2 * c4 + 0) * WP_STRIDE + tx;
        const u64* wb = Wp + (2 * c4 + 1) * WP_STRIDE + tx;
        u64 w0a = wa[0],  w0b = wb[0];
        u64 w1a = wa[32], w1b = wb[32];
        u64 w2a = wa[64], w2b = wb[64];
        u64 w3a = wa[96], w3b = wb[96];
        #pragma unroll
        for (int r = 0; r < 8; r++) {
            ulonglong2 xv = *(const ulonglong2*)(xrow + r * C_DIM + 4 * c4); // bcast
            fma2(acc[r][0], w0a, xv.x); fma2(acc[r][0], w0b, xv.y);
            fma2(acc[r][1], w1a, xv.x); fma2(acc[r][1], w1b, xv.y);
            fma2(acc[r][2], w2a, xv.x); fma2(acc[r][2], w2b, xv.y);
            fma2(acc[r][3], w3a, xv.x); fma2(acc[r][3], w3b, xv.y);
        }
    }
    __syncthreads();   // done reading xs; reuse as output staging

    float bv[4];
    #pragma unroll
    for (int m = 0; m < 4; m++) bv[m] = bias[tx + 32 * m];

    float* res = xs;   // [64][128]
    #pragma unroll
    for (int r = 0; r < 8; r++) {
        #pragma unroll
        for (int m = 0; m < 4; m++) {
            float2 v = unpack2(acc[r][m]);
            float s = v.x + v.y + bv[m];
            res[(ty * 8 + r) * C_DIM + tx + 32 * m] = s > 0.f ? s : 0.2f * s;
        }
    }
    __syncthreads();

    // Coalesced float4 stores: out is write-once -> streaming; g_supports is
    // re-read by att -> default policy (keep in L2).
    #pragma unroll
    for (int i = tid; i < 64 * 32; i += 256) {
        int r  = i >> 5;
        int c4 = i & 31;
        int row = rowBase + r;
        if (row < N) {
            float4 v = ((const float4*)(res + r * C_DIM))[c4];
            __stcs((float4*)(out + (size_t)row * C_DIM) + c4, v);
            ((float4*)(g_supports + (size_t)row * C_DIM))[c4] = v;
        }
    }
}

// ---------------------------------------------------------------------------
// Kernel 2: fused scores -> mask -> softmax -> aggregation -> scatter.
// One block (128 threads) per source s.
// Phase 1 (k,qtr) layout: thread 4k+qtr computes a 32-channel partial dot for
// neighbor k (q staged in smem; neighbor row chunks 64B-coalesced per 4
// lanes), then ONE 2-level shfl pair reduces all 8 neighbors of a warp at
// once: 8 shfl/block vs 160 in the butterfly version.
// Masked-out neighbors skipped (softmax weight is exactly 0 in fp32,
// identical to the reference's exp underflow). All-masked -> uniform 1/32.
// ---------------------------------------------------------------------------
__global__ __launch_bounds__(128) void att_kernel(
    const float* __restrict__ wv,
    const int* __restrict__ src_idx,
    const int* __restrict__ neigh,
    const int* __restrict__ mask,
    float* __restrict__ out,
    int S)
{
    __shared__ float sc[K_NB];
    __shared__ int   nb[K_NB];
    __shared__ int   ms[K_NB];
    __shared__ float qs[C_DIM];

    const int s    = blockIdx.x;
    const int tid  = threadIdx.x;
    const int qtr  = tid & 3;     // channel quarter
    const int kidx = tid >> 2;    // neighbor 0..31

    const int src = src_idx[s];

    // Stage: warp 0 fetches idx+mask, warp 1 stages q row into smem.
    if (tid < 32) {
        nb[tid] = __ldcs(neigh + (size_t)s * K_NB + tid);
        ms[tid] = __ldcs(mask  + (size_t)s * K_NB + tid);
    } else if (tid < 64) {
        int l = tid - 32;
        ((float4*)qs)[l] = ((const float4*)(wv + (size_t)src * C_DIM))[l];
    }
    __syncthreads();

    // Phase 1: partial dot over channels [qtr*32, qtr*32+32).
    const int n = nb[kidx];
    const int m = ms[kidx];
    float part = 0.f;
    if (m) {
        const float4* kr = (const float4*)(wv + (size_t)n * C_DIM) + qtr * 8;
        const float4* qr = (const float4*)qs + qtr * 8;
        #pragma unroll
        for (int i = 0; i < 8; i++) {
            float4 a = qr[i];
            float4 b = kr[i];
            part += a.x * b.x + a.y * b.y + a.z * b.z + a.w * b.w;
        }
    }
    // reduce the 4 quarters (2 shfls serve 8 neighbors per warp)
    part += __shfl_xor_sync(0xffffffffu, part, 1);
    part += __shfl_xor_sync(0xffffffffu, part, 2);
    if (qtr == 0) sc[kidx] = m ? part * 5.0f : -1e6f;
    __syncthreads();

    // Phase 2: warp 0 masked softmax in-place (masked-out probs become 0).
    if (tid < 32) {
        float v = sc[tid];
        bool act = (v != -1e6f);
        unsigned bal = __ballot_sync(0xffffffffu, act);
        float pr;
        if (bal == 0) {
            pr = 1.0f / 32.0f;   // all masked -> uniform (matches reference)
        } else {
            float mx = v;   // inactive lanes hold -1e6, never win the max
            mx = fmaxf(mx, __shfl_xor_sync(0xffffffffu, mx, 16));
            mx = fmaxf(mx, __shfl_xor_sync(0xffffffffu, mx, 8));
            mx = fmaxf(mx, __shfl_xor_sync(0xffffffffu, mx, 4));
            mx = fmaxf(mx, __shfl_xor_sync(0xffffffffu, mx, 2));
            mx = fmaxf(mx, __shfl_xor_sync(0xffffffffu, mx, 1));
            float e = act ? __expf(v - mx) : 0.f;
            float sum = e;
            sum += __shfl_xor_sync(0xffffffffu, sum, 16);
            sum += __shfl_xor_sync(0xffffffffu, sum, 8);
            sum += __shfl_xor_sync(0xffffffffu, sum, 4);
            sum += __shfl_xor_sync(0xffffffffu, sum, 2);
            sum += __shfl_xor_sync(0xffffffffu, sum, 1);
            pr = e / sum;
        }
        sc[tid] = pr;
    }
    __syncthreads();

    // Phase 3: thread = channel; predicated gather over all 32 k (prob==0
    // terms contribute exactly 0 in the reference too).
    const float* sup = g_supports + tid;
    float acc = 0.f;
    #pragma unroll
    for (int j = 0; j < 8; j++) {
        float4 pv = ((const float4*)sc)[j];   // broadcast
        int4   nv = ((const int4*)nb)[j];     // broadcast
        if (pv.x != 0.f) acc = fmaf(pv.x, sup[(size_t)nv.x * C_DIM], acc);
        if (pv.y != 0.f) acc = fmaf(pv.y, sup[(size_t)nv.y * C_DIM], acc);
        if (pv.z != 0.f) acc = fmaf(pv.z, sup[(size_t)nv.z * C_DIM], acc);
        if (pv.w != 0.f) acc = fmaf(pv.w, sup[(size_t)nv.w * C_DIM], acc);
    }
    __stcs(out + (size_t)src * C_DIM + tid, acc);
}

// ---------------------------------------------------------------------------
extern "C" void kernel_launch(void* const* d_in, const int* in_sizes, int n_in,
                              void* d_out, int out_size)
{
    const float* word_vec = (const float*)d_in[0];
    const int*   src_idx  = (const int*)d_in[1];   // int32 from harness
    const int*   neighs   = (const int*)d_in[2];   // int32 from harness
    const int*   src_mask = (const int*)d_in[3];
    const float* W        = (const float*)d_in[4];
    const float* b        = (const float*)d_in[5];
    float*       out      = (float*)d_out;

    const int N = in_sizes[0] / C_DIM;
    const int S = in_sizes[1];

    const int smem_bytes = 64 * WP_STRIDE * 8 + 64 * C_DIM * 4;  // 66048+32768
    cudaFuncSetAttribute(proj_kernel,
                         cudaFuncAttributeMaxDynamicSharedMemorySize, smem_bytes);

    dim3 blk(32, 8);
    proj_kernel<<<(N + 63) / 64, blk, smem_bytes>>>(word_vec, W, b, out, N);

    att_kernel<<<S, 128>>>(word_vec, src_idx, neighs, src_mask, out, S);
}

// round 14
// speedup vs baseline: 1.7246x; 1.7246x over previous
#include <cuda_runtime.h>
#include <cuda_bf16.h>
#include <cstdint>

#define C_DIM 128
#define K_NB  32
#define MAX_N 100000

// Scratch (no-alloc rule: __device__ globals)
__device__ float g_supports[(size_t)MAX_N * C_DIM];

typedef unsigned long long u64;
typedef unsigned int u32;

__device__ __forceinline__ u32 smem_u32(const void* p) {
    u32 a;
    asm("{ .reg .u64 t; cvta.to.shared.u64 t, %1; cvt.u32.u64 %0, t; }"
        : "=r"(a) : "l"(p));
    return a;
}
__device__ __forceinline__ u32 pack_bf16(float a, float b) {
    __nv_bfloat162 h = __floats2bfloat162_rn(a, b);
    return *reinterpret_cast<u32*>(&h);
}

// Blocked-atom SW128 byte offset for a [128 rows][128 bf16] K-major tile.
// atom = 8 rows x 64 bf16 (1024B); 16 atom-rows x 2 atom-cols, stride (1,16).
__device__ __forceinline__ u32 tile_off(int row, int col) {
    u32 off = (u32)((row >> 3) + ((col >> 6) << 4)) * 1024u
            + (u32)(row & 7) * 128u + (u32)(col & 63) * 2u;
    return off ^ ((off >> 3) & 0x70);   // SW128 swizzle (conflict-free ldmatrix)
}

__device__ __forceinline__ void ldsm_x4(u32 addr, u32 &r0, u32 &r1, u32 &r2, u32 &r3) {
    asm volatile("ldmatrix.sync.aligned.m8n8.x4.shared.b16 {%0,%1,%2,%3}, [%4];"
                 : "=r"(r0), "=r"(r1), "=r"(r2), "=r"(r3) : "r"(addr));
}
// m16n8k16 bf16 MMA, fp32 accumulate (sm_80+, arch-agnostic -> compiles for sm_103)
__device__ __forceinline__ void mma16816(float* d,
    u32 a0, u32 a1, u32 a2, u32 a3, u32 b0, u32 b1)
{
    asm volatile("mma.sync.aligned.m16n8k16.row.col.f32.bf16.bf16.f32 "
        "{%0,%1,%2,%3}, {%4,%5,%6,%7}, {%8,%9}, {%0,%1,%2,%3};"
        : "+f"(d[0]), "+f"(d[1]), "+f"(d[2]), "+f"(d[3])
        : "r"(a0), "r"(a1), "r"(a2), "r"(a3), "r"(b0), "r"(b1));
}

// SMEM layout: 4 x 32KB bf16 tiles (x hi/lo, W hi/lo) = 128KB dynamic smem.
#define OFF_XH  0
#define OFF_XL  32768
#define OFF_WH  65536
#define OFF_WL  98304
#define PROJ_SMEM 131072

// ---------------------------------------------------------------------------
// proj: supports = leaky_relu(word_vec @ W^T + b, 0.2) via mma.sync bf16-split.
// fp32 = hi + lo (bf16 each); D = Xh*Wh + Xl*Wh + Xh*Wl (lo*lo ~2^-16, dropped).
// Block: 128 x-rows (M) x 128 out-cols (N). 256 threads = 8 warps; warp w owns
// rows 16w..16w+15, all 128 cols. A = x rows (row-major), B = W rows (K-major
// = col-major B for mma.row.col, so non-trans ldmatrix lands in b-frag layout).
// ---------------------------------------------------------------------------
__global__ __launch_bounds__(256) void proj_kernel(
    const float* __restrict__ x,
    const float* __restrict__ W,
    const float* __restrict__ bias,
    float* __restrict__ out,
    int N)
{
    extern __shared__ char smem[];
    const u32 sb = smem_u32(smem);
    const int tid  = threadIdx.x;
    const int wid  = tid >> 5;
    const int lane = tid & 31;
    const int rowBase = blockIdx.x * 128;

    // Convert W and x tile to bf16 hi/lo in swizzled SMEM.
    #pragma unroll
    for (int i = tid; i < 128 * 32; i += 256) {
        int r = i >> 5, c4 = i & 31, col = c4 * 4;
        u32 off = tile_off(r, col);
        {   // W
            float4 v = ((const float4*)(W + (size_t)r * C_DIM))[c4];
            float r0 = v.x - __bfloat162float(__float2bfloat16(v.x));
            float r1 = v.y - __bfloat162float(__float2bfloat16(v.y));
            float r2 = v.z - __bfloat162float(__float2bfloat16(v.z));
            float r3 = v.w - __bfloat162float(__float2bfloat16(v.w));
            *(u64*)(smem + OFF_WH + off) =
                (u64)pack_bf16(v.x, v.y) | ((u64)pack_bf16(v.z, v.w) << 32);
            *(u64*)(smem + OFF_WL + off) =
                (u64)pack_bf16(r0, r1) | ((u64)pack_bf16(r2, r3) << 32);
        }
        {   // x (zero-padded tail)
            int row = rowBase + r;
            float4 v = make_float4(0.f, 0.f, 0.f, 0.f);
            if (row < N) v = ((const float4*)(x + (size_t)row * C_DIM))[c4];
            float r0 = v.x - __bfloat162float(__float2bfloat16(v.x));
            float r1 = v.y - __bfloat162float(__float2bfloat16(v.y));
            float r2 = v.z - __bfloat162float(__float2bfloat16(v.z));
            float r3 = v.w - __bfloat162float(__float2bfloat16(v.w));
            *(u64*)(smem + OFF_XH + off) =
                (u64)pack_bf16(v.x, v.y) | ((u64)pack_bf16(v.z, v.w) << 32);
            *(u64*)(smem + OFF_XL + off) =
                (u64)pack_bf16(r0, r1) | ((u64)pack_bf16(r2, r3) << 32);
        }
    }
    __syncthreads();

    float d[16][4];
    #pragma unroll
    for (int nf = 0; nf < 16; nf++)
        #pragma unroll
        for (int j = 0; j < 4; j++) d[nf][j] = 0.f;

    const int m0 = wid * 16;
    const int g  = lane >> 3;   // ldmatrix matrix group 0..3
    const int r8 = lane & 7;    // row within matrix

    #pragma unroll
    for (int ks = 0; ks < 8; ks++) {
        const int k0 = ks * 16;
        // A lane address: matrix g -> rows m0+(g&1)*8, k-chunk (g>>1)*8
        const u32 a_off = tile_off(m0 + (g & 1) * 8 + r8, k0 + (g >> 1) * 8);
        u32 ah0, ah1, ah2, ah3, al0, al1, al2, al3;
        ldsm_x4(sb + OFF_XH + a_off, ah0, ah1, ah2, ah3);
        ldsm_x4(sb + OFF_XL + a_off, al0, al1, al2, al3);

        #pragma unroll
        for (int np = 0; np < 8; np++) {
            // B lane address: matrix g -> n-rows 16np+(g&2)*4, k-chunk (g&1)*8
            const u32 b_off = tile_off(16 * np + (g & 2) * 4 + r8, k0 + (g & 1) * 8);
            u32 bh0, bh1, bh2, bh3, bl0, bl1, bl2, bl3;
            ldsm_x4(sb + OFF_WH + b_off, bh0, bh1, bh2, bh3);
            ldsm_x4(sb + OFF_WL + b_off, bl0, bl1, bl2, bl3);
            // nf = 2np: b-frag {bh0,bh1}; nf = 2np+1: {bh2,bh3}
            mma16816(d[2 * np],     ah0, ah1, ah2, ah3, bh0, bh1);
            mma16816(d[2 * np],     al0, al1, al2, al3, bh0, bh1);
            mma16816(d[2 * np],     ah0, ah1, ah2, ah3, bl0, bl1);
            mma16816(d[2 * np + 1], ah0, ah1, ah2, ah3, bh2, bh3);
            mma16816(d[2 * np + 1], al0, al1, al2, al3, bh2, bh3);
            mma16816(d[2 * np + 1], ah0, ah1, ah2, ah3, bl2, bl3);
        }
    }

    // Epilogue: d-frag lane l -> rows m0+(l>>2), m0+8+(l>>2); cols 8nf+2(l&3)+{0,1}.
    // STG.64 per row-half: 8 rows x 32B full sectors per warp instruction.
    const int rlo = rowBase + m0 + (lane >> 2);
    const int rhi = rlo + 8;
    #pragma unroll
    for (int nf = 0; nf < 16; nf++) {
        const int c0 = nf * 8 + 2 * (lane & 3);
        const float b0 = bias[c0], b1 = bias[c0 + 1];
        float v0 = d[nf][0] + b0; v0 = v0 > 0.f ? v0 : 0.2f * v0;
        float v1 = d[nf][1] + b1; v1 = v1 > 0.f ? v1 : 0.2f * v1;
        float v2 = d[nf][2] + b0; v2 = v2 > 0.f ? v2 : 0.2f * v2;
        float v3 = d[nf][3] + b1; v3 = v3 > 0.f ? v3 : 0.2f * v3;
        if (rlo < N) {
            float2 p = make_float2(v0, v1);
            __stcs((float2*)(out + (size_t)rlo * C_DIM + c0), p);
            *(float2*)(g_supports + (size_t)rlo * C_DIM + c0) = p;
        }
        if (rhi < N) {
            float2 p = make_float2(v2, v3);
            __stcs((float2*)(out + (size_t)rhi * C_DIM + c0), p);
            *(float2*)(g_supports + (size_t)rhi * C_DIM + c0) = p;
        }
    }
}

// ---------------------------------------------------------------------------
// Kernel 2 (round-10 form, measured 136us): fused scores -> mask -> softmax ->
// aggregation -> scatter. One block (128 threads = 4 warps) per source s.
// ---------------------------------------------------------------------------
__global__ __launch_bounds__(128) void att_kernel(
    const float* __restrict__ wv,
    const int* __restrict__ src_idx,
    const int* __restrict__ neigh,
    const int* __restrict__ mask,
    float* __restrict__ out,
    int S)
{
    __shared__ float sc[K_NB];
    __shared__ int   nb[K_NB];

    const int s    = blockIdx.x;
    const int tid  = threadIdx.x;
    const int w    = tid >> 5;
    const int lane = tid & 31;
    const int k0   = w * 8;

    const int src = src_idx[s];
    const float4 q = ((const float4*)(wv + (size_t)src * C_DIM))[lane];

    int myn = 0, mym = 0;
    if (lane < 8) {
        myn = __ldcs(neigh + (size_t)s * K_NB + k0 + lane);
        mym = __ldcs(mask  + (size_t)s * K_NB + k0 + lane);
        nb[k0 + lane] = myn;
    }

    float p[8];
    int   mk[8];
    #pragma unroll
    for (int kk = 0; kk < 8; kk++) {
        int nk = __shfl_sync(0xffffffffu, myn, kk);
        mk[kk] = __shfl_sync(0xffffffffu, mym, kk);
        if (mk[kk]) {   // warp-uniform branch
            float4 kv = ((const float4*)(wv + (size_t)nk * C_DIM))[lane];
            p[kk] = q.x * kv.x + q.y * kv.y + q.z * kv.z + q.w * kv.w;
        } else {
            p[kk] = 0.f;
        }
    }
    #pragma unroll
    for (int lvl = 16; lvl > 0; lvl >>= 1) {
        #pragma unroll
        for (int kk = 0; kk < 8; kk++)
            p[kk] += __shfl_xor_sync(0xffffffffu, p[kk], lvl);
    }
    if (lane == 0) {
        #pragma unroll
        for (int kk = 0; kk < 8; kk++)
            sc[k0 + kk] = mk[kk] ? p[kk] * 5.0f : -1e6f;
    }
    __syncthreads();

    if (tid < 32) {
        float v = sc[tid];
        bool act = (v != -1e6f);
        unsigned bal = __ballot_sync(0xffffffffu, act);
        float pr;
        if (bal == 0) {
            pr = 1.0f / 32.0f;   // all masked -> uniform (matches reference)
        } else {
            float m = v;
            m = fmaxf(m, __shfl_xor_sync(0xffffffffu, m, 16));
            m = fmaxf(m, __shfl_xor_sync(0xffffffffu, m, 8));
            m = fmaxf(m, __shfl_xor_sync(0xffffffffu, m, 4));
            m = fmaxf(m, __shfl_xor_sync(0xffffffffu, m, 2));
            m = fmaxf(m, __shfl_xor_sync(0xffffffffu, m, 1));
            float e = act ? __expf(v - m) : 0.f;
            float sum = e;
            sum += __shfl_xor_sync(0xffffffffu, sum, 16);
            sum += __shfl_xor_sync(0xffffffffu, sum, 8);
            sum += __shfl_xor_sync(0xffffffffu, sum, 4);
            sum += __shfl_xor_sync(0xffffffffu, sum, 2);
            sum += __shfl_xor_sync(0xffffffffu, sum, 1);
            pr = e / sum;
        }
        sc[tid] = pr;
    }
    __syncthreads();

    const float* sup = g_supports + tid;
    float acc = 0.f;
    #pragma unroll
    for (int j = 0; j < 8; j++) {
        float4 pv = ((const float4*)sc)[j];   // broadcast
        int4   nv = ((const int4*)nb)[j];     // broadcast
        if (pv.x != 0.f) acc = fmaf(pv.x, sup[(size_t)nv.x * C_DIM], acc);
        if (pv.y != 0.f) acc = fmaf(pv.y, sup[(size_t)nv.y * C_DIM], acc);
        if (pv.z != 0.f) acc = fmaf(pv.z, sup[(size_t)nv.z * C_DIM], acc);
        if (pv.w != 0.f) acc = fmaf(pv.w, sup[(size_t)nv.w * C_DIM], acc);
    }
    __stcs(out + (size_t)src * C_DIM + tid, acc);
}

// ---------------------------------------------------------------------------
extern "C" void kernel_launch(void* const* d_in, const int* in_sizes, int n_in,
                              void* d_out, int out_size)
{
    const float* word_vec = (const float*)d_in[0];
    const int*   src_idx  = (const int*)d_in[1];   // int32 from harness
    const int*   neighs   = (const int*)d_in[2];   // int32 from harness
    const int*   src_mask = (const int*)d_in[3];
    const float* W        = (const float*)d_in[4];
    const float* b        = (const float*)d_in[5];
    float*       out      = (float*)d_out;

    const int N = in_sizes[0] / C_DIM;
    const int S = in_sizes[1];

    cudaFuncSetAttribute(proj_kernel,
                         cudaFuncAttributeMaxDynamicSharedMemorySize, PROJ_SMEM);

    proj_kernel<<<(N + 127) / 128, 256, PROJ_SMEM>>>(word_vec, W, b, out, N);

    att_kernel<<<S, 128>>>(word_vec, src_idx, neighs, src_mask, out, S);
}

// round 17
// speedup vs baseline: 1.7459x; 1.0124x over previous
#include <cuda_runtime.h>
#include <cuda_bf16.h>
#include <cstdint>

#define C_DIM 128
#define K_NB  32
#define MAX_N 100000

// Scratch (no-alloc rule: __device__ globals)
__device__ float g_supports[(size_t)MAX_N * C_DIM];

typedef unsigned long long u64;
typedef unsigned int u32;

__device__ __forceinline__ u32 smem_u32(const void* p) {
    u32 a;
    asm("{ .reg .u64 t; cvta.to.shared.u64 t, %1; cvt.u32.u64 %0, t; }"
        : "=r"(a) : "l"(p));
    return a;
}
__device__ __forceinline__ u32 pack_bf16(float a, float b) {
    __nv_bfloat162 h = __floats2bfloat162_rn(a, b);
    return *reinterpret_cast<u32*>(&h);
}

// Blocked-atom SW128 byte offset for a [128 rows][128 bf16] K-major tile.
__device__ __forceinline__ u32 tile_off(int row, int col) {
    u32 off = (u32)((row >> 3) + ((col >> 6) << 4)) * 1024u
            + (u32)(row & 7) * 128u + (u32)(col & 63) * 2u;
    return off ^ ((off >> 3) & 0x70);   // SW128 swizzle (conflict-free ldmatrix)
}

__device__ __forceinline__ void ldsm_x4(u32 addr, u32 &r0, u32 &r1, u32 &r2, u32 &r3) {
    asm volatile("ldmatrix.sync.aligned.m8n8.x4.shared.b16 {%0,%1,%2,%3}, [%4];"
                 : "=r"(r0), "=r"(r1), "=r"(r2), "=r"(r3) : "r"(addr));
}
__device__ __forceinline__ void mma16816(float* d,
    u32 a0, u32 a1, u32 a2, u32 a3, u32 b0, u32 b1)
{
    asm volatile("mma.sync.aligned.m16n8k16.row.col.f32.bf16.bf16.f32 "
        "{%0,%1,%2,%3}, {%4,%5,%6,%7}, {%8,%9}, {%0,%1,%2,%3};"
        : "+f"(d[0]), "+f"(d[1]), "+f"(d[2]), "+f"(d[3])
        : "r"(a0), "r"(a1), "r"(a2), "r"(a3), "r"(b0), "r"(b1));
}

#define OFF_XH  0
#define OFF_XL  32768
#define OFF_WH  65536
#define OFF_WL  98304
#define PROJ_SMEM 131072

// ---------------------------------------------------------------------------
// proj (round-14 form, measured ~50us): mma.sync bf16-split GEMM.
// D = Xh*Wh + Xl*Wh + Xh*Wl, fp32 accumulate; error ~2^-16.
// ---------------------------------------------------------------------------
__global__ __launch_bounds__(256) void proj_kernel(
    const float* __restrict__ x,
    const float* __restrict__ W,
    const float* __restrict__ bias,
    float* __restrict__ out,
    int N)
{
    extern __shared__ char smem[];
    const u32 sb = smem_u32(smem);
    const int tid  = threadIdx.x;
    const int wid  = tid >> 5;
    const int lane = tid & 31;
    const int rowBase = blockIdx.x * 128;

    #pragma unroll
    for (int i = tid; i < 128 * 32; i += 256) {
        int r = i >> 5, c4 = i & 31, col = c4 * 4;
        u32 off = tile_off(r, col);
        {   // W
            float4 v = ((const float4*)(W + (size_t)r * C_DIM))[c4];
            float r0 = v.x - __bfloat162float(__float2bfloat16(v.x));
            float r1 = v.y - __bfloat162float(__float2bfloat16(v.y));
            float r2 = v.z - __bfloat162float(__float2bfloat16(v.z));
            float r3 = v.w - __bfloat162float(__float2bfloat16(v.w));
            *(u64*)(smem + OFF_WH + off) =
                (u64)pack_bf16(v.x, v.y) | ((u64)pack_bf16(v.z, v.w) << 32);
            *(u64*)(smem + OFF_WL + off) =
                (u64)pack_bf16(r0, r1) | ((u64)pack_bf16(r2, r3) << 32);
        }
        {   // x (zero-padded tail)
            int row = rowBase + r;
            float4 v = make_float4(0.f, 0.f, 0.f, 0.f);
            if (row < N) v = ((const float4*)(x + (size_t)row * C_DIM))[c4];
            float r0 = v.x - __bfloat162float(__float2bfloat16(v.x));
            float r1 = v.y - __bfloat162float(__float2bfloat16(v.y));
            float r2 = v.z - __bfloat162float(__float2bfloat16(v.z));
            float r3 = v.w - __bfloat162float(__float2bfloat16(v.w));
            *(u64*)(smem + OFF_XH + off) =
                (u64)pack_bf16(v.x, v.y) | ((u64)pack_bf16(v.z, v.w) << 32);
            *(u64*)(smem + OFF_XL + off) =
                (u64)pack_bf16(r0, r1) | ((u64)pack_bf16(r2, r3) << 32);
        }
    }
    __syncthreads();

    float d[16][4];
    #pragma unroll
    for (int nf = 0; nf < 16; nf++)
        #pragma unroll
        for (int j = 0; j < 4; j++) d[nf][j] = 0.f;

    const int m0 = wid * 16;
    const int g  = lane >> 3;
    const int r8 = lane & 7;

    #pragma unroll
    for (int ks = 0; ks < 8; ks++) {
        const int k0 = ks * 16;
        const u32 a_off = tile_off(m0 + (g & 1) * 8 + r8, k0 + (g >> 1) * 8);
        u32 ah0, ah1, ah2, ah3, al0, al1, al2, al3;
        ldsm_x4(sb + OFF_XH + a_off, ah0, ah1, ah2, ah3);
        ldsm_x4(sb + OFF_XL + a_off, al0, al1, al2, al3);

        #pragma unroll
        for (int np = 0; np < 8; np++) {
            const u32 b_off = tile_off(16 * np + (g & 2) * 4 + r8, k0 + (g & 1) * 8);
            u32 bh0, bh1, bh2, bh3, bl0, bl1, bl2, bl3;
            ldsm_x4(sb + OFF_WH + b_off, bh0, bh1, bh2, bh3);
            ldsm_x4(sb + OFF_WL + b_off, bl0, bl1, bl2, bl3);
            mma16816(d[2 * np],     ah0, ah1, ah2, ah3, bh0, bh1);
            mma16816(d[2 * np],     al0, al1, al2, al3, bh0, bh1);
            mma16816(d[2 * np],     ah0, ah1, ah2, ah3, bl0, bl1);
            mma16816(d[2 * np + 1], ah0, ah1, ah2, ah3, bh2, bh3);
            mma16816(d[2 * np + 1], al0, al1, al2, al3, bh2, bh3);
            mma16816(d[2 * np + 1], ah0, ah1, ah2, ah3, bl2, bl3);
        }
    }

    const int rlo = rowBase + m0 + (lane >> 2);
    const int rhi = rlo + 8;
    #pragma unroll
    for (int nf = 0; nf < 16; nf++) {
        const int c0 = nf * 8 + 2 * (lane & 3);
        const float b0 = bias[c0], b1 = bias[c0 + 1];
        float v0 = d[nf][0] + b0; v0 = v0 > 0.f ? v0 : 0.2f * v0;
        float v1 = d[nf][1] + b1; v1 = v1 > 0.f ? v1 : 0.2f * v1;
        float v2 = d[nf][2] + b0; v2 = v2 > 0.f ? v2 : 0.2f * v2;
        float v3 = d[nf][3] + b1; v3 = v3 > 0.f ? v3 : 0.2f * v3;
        if (rlo < N) {
            float2 p = make_float2(v0, v1);
            __stcs((float2*)(out + (size_t)rlo * C_DIM + c0), p);
            *(float2*)(g_supports + (size_t)rlo * C_DIM + c0) = p;
        }
        if (rhi < N) {
            float2 p = make_float2(v2, v3);
            __stcs((float2*)(out + (size_t)rhi * C_DIM + c0), p);
            *(float2*)(g_supports + (size_t)rhi * C_DIM + c0) = p;
        }
    }
}

// ---------------------------------------------------------------------------
// Kernel 2: fused scores -> mask -> softmax -> aggregation -> scatter.
// One block (128 threads = 4 warps) per source s.
// SHFL diet vs round 14 (shfl shares the l1tex/LSU datapath = the 74% SOL):
//  - (neighbor, mask) packed into one word -> 8 broadcast shfls, not 16
//  - dot reduction by register-packing: 8 regs -> 4 -> 2 -> 1 splitting lanes
//    on bits 16/8/4, then xor2+xor1: 9 shfls instead of the 40-shfl butterfly.
//    Final mapping: lane holds S_k for k = b16*4 + b8*2 + b4.
// ---------------------------------------------------------------------------
__global__ __launch_bounds__(128) void att_kernel(
    const float* __restrict__ wv,
    const int* __restrict__ src_idx,
    const int* __restrict__ neigh,
    const int* __restrict__ mask,
    float* __restrict__ out,
    int S)
{
    __shared__ float sc[K_NB];
    __shared__ int   nb[K_NB];

    const int s    = blockIdx.x;
    const int tid  = threadIdx.x;
    const int w    = tid >> 5;
    const int lane = tid & 31;
    const int k0   = w * 8;
    const unsigned FULL = 0xffffffffu;

    const int src = src_idx[s];
    const float4 q = ((const float4*)(wv + (size_t)src * C_DIM))[lane];

    // lanes 0..7: load neighbor + mask, pack as n | (m<<30)
    u32 myv = 0;
    if (lane < 8) {
        int n = __ldcs(neigh + (size_t)s * K_NB + k0 + lane);
        int m = __ldcs(mask  + (size_t)s * K_NB + k0 + lane);
        myv = (u32)n | ((u32)m << 30);
        nb[k0 + lane] = n;
    }

    float p[8];
    #pragma unroll
    for (int kk = 0; kk < 8; kk++) {
        u32 v = __shfl_sync(FULL, myv, kk);
        if (v >> 30) {   // warp-uniform branch
            int nk = (int)(v & 0x3FFFFFFFu);
            float4 kv = ((const float4*)(wv + (size_t)nk * C_DIM))[lane];
            p[kk] = q.x * kv.x + q.y * kv.y + q.z * kv.z + q.w * kv.w;
        } else {
            p[kk] = 0.f;
        }
    }

    // Packing reduction: 9 shfls total.
    float z[4];
    {
        const bool hi16 = (lane & 16) != 0;
        #pragma unroll
        for (int k = 0; k < 4; k++) {
            float t = hi16 ? p[k + 4] : p[k];
            float u = hi16 ? p[k] : p[k + 4];
            z[k] = t + __shfl_xor_sync(FULL, u, 16);
        }
    }
    float y[2];
    {
        const bool hi8 = (lane & 8) != 0;
        #pragma unroll
        for (int j = 0; j < 2; j++) {
            float t = hi8 ? z[j + 2] : z[j];
            float u = hi8 ? z[j] : z[j + 2];
            y[j] = t + __shfl_xor_sync(FULL, u, 8);
        }
    }
    float acc8;
    {
        const bool hi4 = (lane & 4) != 0;
        float t = hi4 ? y[1] : y[0];
        float u = hi4 ? y[0] : y[1];
        acc8 = t + __shfl_xor_sync(FULL, u, 4);
    }
    acc8 += __shfl_xor_sync(FULL, acc8, 2);
    acc8 += __shfl_xor_sync(FULL, acc8, 1);

    // lane's k: b16*4 + b8*2 + b4
    const int myk = ((lane >> 4) & 1) * 4 + ((lane >> 3) & 1) * 2 + ((lane >> 2) & 1);
    u32 vk = __shfl_sync(FULL, myv, myk);   // packed word of neighbor myk
    if ((lane & 3) == 0)
        sc[k0 + myk] = (vk >> 30) ? acc8 * 5.0f : -1e6f;
    __syncthreads();

    // warp 0: masked softmax (masked-out probs become exactly 0)
    if (tid < 32) {
        float v = sc[tid];
        bool act = (v != -1e6f);
        unsigned bal = __ballot_sync(FULL, act);
        float pr;
        if (bal == 0) {
            pr = 1.0f / 32.0f;   // all masked -> uniform (matches reference)
        } else {
            float m = v;
            m = fmaxf(m, __shfl_xor_sync(FULL, m, 16));
            m = fmaxf(m, __shfl_xor_sync(FULL, m, 8));
            m = fmaxf(m, __shfl_xor_sync(FULL, m, 4));
            m = fmaxf(m, __shfl_xor_sync(FULL, m, 2));
            m = fmaxf(m, __shfl_xor_sync(FULL, m, 1));
            float e = act ? __expf(v - m) : 0.f;
            float sum = e;
            sum += __shfl_xor_sync(FULL, sum, 16);
            sum += __shfl_xor_sync(FULL, sum, 8);
            sum += __shfl_xor_sync(FULL, sum, 4);
            sum += __shfl_xor_sync(FULL, sum, 2);
            sum += __shfl_xor_sync(FULL, sum, 1);
            pr = e / sum;
        }
        sc[tid] = pr;
    }
    __syncthreads();

    // thread = channel; predicated gather over all 32 k
    const float* sup = g_supports + tid;
    float acc = 0.f;
    #pragma unroll
    for (int j = 0; j < 8; j++) {
        float4 pv = ((const float4*)sc)[j];   // broadcast
        int4   nv = ((const int4*)nb)[j];     // broadcast
        if (pv.x != 0.f) acc = fmaf(pv.x, sup[(size_t)nv.x * C_DIM], acc);
        if (pv.y != 0.f) acc = fmaf(pv.y, sup[(size_t)nv.y * C_DIM], acc);
        if (pv.z != 0.f) acc = fmaf(pv.z, sup[(size_t)nv.z * C_DIM], acc);
        if (pv.w != 0.f) acc = fmaf(pv.w, sup[(size_t)nv.w * C_DIM], acc);
    }
    __stcs(out + (size_t)src * C_DIM + tid, acc);
}

// ---------------------------------------------------------------------------
extern "C" void kernel_launch(void* const* d_in, const int* in_sizes, int n_in,
                              void* d_out, int out_size)
{
    const float* word_vec = (const float*)d_in[0];
    const int*   src_idx  = (const int*)d_in[1];   // int32 from harness
    const int*   neighs   = (const int*)d_in[2];   // int32 from harness
    const int*   src_mask = (const int*)d_in[3];
    const float* W        = (const float*)d_in[4];
    const float* b        = (const float*)d_in[5];
    float*       out      = (float*)d_out;

    const int N = in_sizes[0] / C_DIM;
    const int S = in_sizes[1];

    cudaFuncSetAttribute(proj_kernel,
                         cudaFuncAttributeMaxDynamicSharedMemorySize, PROJ_SMEM);

    proj_kernel<<<(N + 127) / 128, 256, PROJ_SMEM>>>(word_vec, W, b, out, N);

    att_kernel<<<S, 128>>>(word_vec, src_idx, neighs, src_mask, out, S);
}